// round 7
// baseline (speedup 1.0000x reference)
#include <cuda_runtime.h>
#include <cstdint>

// ---------------- problem constants ----------------
#define T_TOK 8192
#define DIN   4096
#define DOUT  4096
#define CL    256                  // NUM_ADAPTERS * MAX_RANK pages
#define KSEGQ (DIN + CL)           // 4352 bytes per int8 plane (x | xa)
#define KSTRQ (2 * KSEGQ)          // 8704 row stride: [plane1 | plane2]
#define BKQ   32                   // 32 int8 per chunk = one m16n8k32
#define CH_MAIN  (KSEGQ / BKQ)     // 136 chunks (X1W1)
#define CH_CROSS (2 * CH_MAIN)     // 272 chunks (X1W2 then X2W1)

#define SSTR   48                  // smem row stride bytes (conflict-free LDSM)
#define ATILE  (128 * SSTR)        // 6144 B per A (or B) stage tile
#define STAGE  (2 * ATILE)         // 12288 B per pipeline stage
#define NST    4
#define DSMEM  (NST * STAGE)       // 49152 B

// quantization scales (fixed conservative bounds + clamping)
#define SXQ (8.0f / 127.0f)        // x / xa plane scale      (|x|,|xa| < 8)
#define SWQ (0.125f / 127.0f)      // weight-class plane scale (|w|,|a|,|b| < 0.125)
#define S_MAIN  (SXQ * SWQ)
#define S_CROSS (SXQ * SWQ / 128.0f)

// ---------------- device scratch (no allocs; zero-initialized) ----------------
// Aq row t: [X1(4096) | XA1(256) | X2(4096) | XA2(256)]
__device__ signed char g_Aq[(size_t)T_TOK * KSTRQ];
// Bq row n: [W1 | BT1 | W2 | BT2]
__device__ signed char g_Bq[(size_t)DOUT * KSTRQ];
// B1q row j: [A1cat | 0(256) | A2cat | 0(256)]   (zero slots never written)
__device__ signed char g_B1q[(size_t)CL * KSTRQ];
// gemm1 output (fp32): routed low-rank activations
__device__ float g_xa[(size_t)T_TOK * CL];

// ---------------- generic-PTX helpers (sm_80+) ----------------
__device__ __forceinline__ uint32_t smem_u32(const void* p) {
    uint32_t a;
    asm("{ .reg .u64 t; cvta.to.shared.u64 t, %1; cvt.u32.u64 %0, t; }" : "=r"(a) : "l"(p));
    return a;
}
__device__ __forceinline__ void cp_async16(uint32_t saddr, const void* gaddr) {
    asm volatile("cp.async.cg.shared.global [%0], [%1], 16;" :: "r"(saddr), "l"(gaddr));
}
__device__ __forceinline__ void cp_commit() { asm volatile("cp.async.commit_group;"); }
__device__ __forceinline__ void cp_wait2()  { asm volatile("cp.async.wait_group 2;" ::: "memory"); }
__device__ __forceinline__ void cp_wait0()  { asm volatile("cp.async.wait_group 0;" ::: "memory"); }

__device__ __forceinline__ void ldm_x4(uint32_t* r, uint32_t addr) {
    asm volatile("ldmatrix.sync.aligned.m8n8.x4.shared.b16 {%0,%1,%2,%3}, [%4];"
                 : "=r"(r[0]), "=r"(r[1]), "=r"(r[2]), "=r"(r[3]) : "r"(addr));
}
__device__ __forceinline__ void ldm_x2(uint32_t* r, uint32_t addr) {
    asm volatile("ldmatrix.sync.aligned.m8n8.x2.shared.b16 {%0,%1}, [%2];"
                 : "=r"(r[0]), "=r"(r[1]) : "r"(addr));
}
// s8 m16n8k32: fragments are byte-identical to bf16 m16n8k16 fragments.
__device__ __forceinline__ void imma16832(int* c, const uint32_t* a, const uint32_t* b) {
    asm volatile(
        "mma.sync.aligned.m16n8k32.row.col.s32.s8.s8.s32 "
        "{%0,%1,%2,%3}, {%4,%5,%6,%7}, {%8,%9}, {%0,%1,%2,%3};"
        : "+r"(c[0]), "+r"(c[1]), "+r"(c[2]), "+r"(c[3])
        : "r"(a[0]), "r"(a[1]), "r"(a[2]), "r"(a[3]), "r"(b[0]), "r"(b[1]));
}

// ---------------- quantization helper ----------------
__device__ __forceinline__ void quant2(float v, float inv_s, signed char& q1, signed char& q2) {
    float t  = v * inv_s;
    float r1 = rintf(t);
    r1 = fminf(fmaxf(r1, -127.0f), 127.0f);
    float r2 = rintf((t - r1) * 128.0f);
    r2 = fminf(fmaxf(r2, -127.0f), 127.0f);
    q1 = (signed char)r1;
    q2 = (signed char)r2;
}

// ---------------- packing kernels ----------------
__global__ void pack_x(const float* __restrict__ x) {
    size_t i4 = ((size_t)blockIdx.x * blockDim.x + threadIdx.x) * 4;
    size_t t = i4 / DIN, k = i4 % DIN;
    float4 v = *(const float4*)(x + i4);
    char4 p1, p2;
    quant2(v.x, 127.0f / 8.0f, p1.x, p2.x);
    quant2(v.y, 127.0f / 8.0f, p1.y, p2.y);
    quant2(v.z, 127.0f / 8.0f, p1.z, p2.z);
    quant2(v.w, 127.0f / 8.0f, p1.w, p2.w);
    signed char* row = g_Aq + t * KSTRQ;
    *(char4*)(row + k) = p1;
    *(char4*)(row + KSEGQ + k) = p2;
}
__global__ void pack_w(const float* __restrict__ w) {
    size_t i4 = ((size_t)blockIdx.x * blockDim.x + threadIdx.x) * 4;
    size_t n = i4 / DIN, k = i4 % DIN;
    float4 v = *(const float4*)(w + i4);
    char4 p1, p2;
    quant2(v.x, 127.0f / 0.125f, p1.x, p2.x);
    quant2(v.y, 127.0f / 0.125f, p1.y, p2.y);
    quant2(v.z, 127.0f / 0.125f, p1.z, p2.z);
    quant2(v.w, 127.0f / 0.125f, p1.w, p2.w);
    signed char* row = g_Bq + n * KSTRQ;
    *(char4*)(row + k) = p1;
    *(char4*)(row + KSEGQ + k) = p2;
}
__global__ void pack_bt(const float* __restrict__ b_cache, const int* __restrict__ page) {
    size_t idx = (size_t)blockIdx.x * blockDim.x + threadIdx.x;   // DOUT*CL/4 threads
    size_t n = idx / (CL / 4), j = (idx % (CL / 4)) * 4;
    char4 p1, p2;
    quant2(b_cache[(size_t)page[j + 0] * DOUT + n], 127.0f / 0.125f, p1.x, p2.x);
    quant2(b_cache[(size_t)page[j + 1] * DOUT + n], 127.0f / 0.125f, p1.y, p2.y);
    quant2(b_cache[(size_t)page[j + 2] * DOUT + n], 127.0f / 0.125f, p1.z, p2.z);
    quant2(b_cache[(size_t)page[j + 3] * DOUT + n], 127.0f / 0.125f, p1.w, p2.w);
    signed char* row = g_Bq + n * KSTRQ;
    *(char4*)(row + DIN + j) = p1;
    *(char4*)(row + KSEGQ + DIN + j) = p2;
}
__global__ void pack_b1(const float* __restrict__ a_cache, const int* __restrict__ page,
                        const int* __restrict__ ranks) {
    size_t i4 = ((size_t)blockIdx.x * blockDim.x + threadIdx.x) * 4;
    size_t j = i4 / DIN, k = i4 % DIN;
    int a = (int)(j >> 6), r = (int)(j & 63);
    float am = (r < ranks[a]) ? 1.0f : 0.0f;
    float4 v = *(const float4*)(a_cache + (size_t)page[j] * DIN + k);
    char4 p1, p2;
    quant2(am * v.x, 127.0f / 0.125f, p1.x, p2.x);
    quant2(am * v.y, 127.0f / 0.125f, p1.y, p2.y);
    quant2(am * v.z, 127.0f / 0.125f, p1.z, p2.z);
    quant2(am * v.w, 127.0f / 0.125f, p1.w, p2.w);
    signed char* row = g_B1q + j * KSTRQ;
    *(char4*)(row + k) = p1;
    *(char4*)(row + KSEGQ + k) = p2;
}
__global__ void pack_xa() {
    size_t i4 = ((size_t)blockIdx.x * blockDim.x + threadIdx.x) * 4;
    size_t t = i4 / CL, j = i4 % CL;
    float4 v = *(const float4*)(g_xa + i4);
    char4 p1, p2;
    quant2(v.x, 127.0f / 8.0f, p1.x, p2.x);
    quant2(v.y, 127.0f / 8.0f, p1.y, p2.y);
    quant2(v.z, 127.0f / 8.0f, p1.z, p2.z);
    quant2(v.w, 127.0f / 8.0f, p1.w, p2.w);
    signed char* row = g_Aq + t * KSTRQ;
    *(char4*)(row + DIN + j) = p1;
    *(char4*)(row + KSEGQ + DIN + j) = p2;
}

// ---------------- int8 IMMA GEMM pass ----------------
// CTA 128x128, BKQ=32 int8, 8 warps (2x4), warp tile 64x32, m16n8k32 s8 -> s32.
// 4-stage cp.async pipeline, arithmetic stage addressing.
// CROSS=false: C = scale*acc (+bias if !MASK), K map (c, c).
// CROSS=true : C += scale*acc, K map (X1,W2) then (X2,W1).
// MASK: gemm1 adapter-routing mask on output columns.
template <bool MASK, bool CROSS>
__global__ __launch_bounds__(256, 2)
void imma_gemm(const signed char* __restrict__ A,
               const signed char* __restrict__ B,
               const float* __restrict__ bias,
               const int* __restrict__ adapter_ids,
               float* __restrict__ C, int ldc, float scale)
{
    extern __shared__ char dsm[];
    const int NCH = CROSS ? CH_CROSS : CH_MAIN;

    const int tid  = threadIdx.x;
    const int lane = tid & 31;
    const int wid  = tid >> 5;
    const int wm   = wid >> 2;          // 0..1 -> warp row (64 rows)
    const int wn   = wid & 3;           // 0..3 -> warp col (32 cols)
    const int bm   = blockIdx.y * 128;
    const int bn   = blockIdx.x * 128;

    // tile fill: 128 rows x 2 16B-units per operand; thread -> (row, unit)
    const int rr = tid >> 1, un = tid & 1;
    const signed char* Ag = A + (size_t)(bm + rr) * KSTRQ + un * 16;
    const signed char* Bg = B + (size_t)(bn + rr) * KSTRQ + un * 16;

    const uint32_t dbase = smem_u32(dsm);
    const uint32_t offA  = rr * SSTR + un * 16;
    const uint32_t offB  = ATILE + offA;
    // ldmatrix bases (byte-identical to validated bf16 wiring, SSTR=48):
    // A x4: row = wm*64 + (lane&15), halfsel = (lane>>4)*16 bytes
    // B x2: row = wn*32 + (lane&7),  halfsel = ((lane>>3)&1)*16 bytes
    const uint32_t aOff = (wm * 64 + (lane & 15)) * SSTR + (lane >> 4) * 16;
    const uint32_t bOff = ATILE + (wn * 32 + (lane & 7)) * SSTR + ((lane >> 3) & 1) * 16;

    int acc[4][4][4];
#pragma unroll
    for (int mi = 0; mi < 4; ++mi)
#pragma unroll
        for (int ni = 0; ni < 4; ++ni)
#pragma unroll
            for (int q = 0; q < 4; ++q) acc[mi][ni][q] = 0;

    auto issue_loads = [&](int c, int s) {
        const uint32_t st = dbase + (uint32_t)s * STAGE;
        size_t ka, kb;
        if (CROSS) {
            if (c < CH_MAIN) { ka = (size_t)c * BKQ;            kb = KSEGQ + (size_t)c * BKQ; }
            else             { ka = KSEGQ + (size_t)(c - CH_MAIN) * BKQ; kb = (size_t)(c - CH_MAIN) * BKQ; }
        } else {
            ka = (size_t)c * BKQ; kb = ka;
        }
        cp_async16(st + offA, Ag + ka);
        cp_async16(st + offB, Bg + kb);
        cp_commit();
    };

    // prologue: 3 stages in flight
    issue_loads(0, 0);
    issue_loads(1, 1);
    issue_loads(2, 2);

    for (int c = 0; c < NCH; ++c) {
        const int s = c & 3;
        if (c + 3 < NCH) cp_wait2(); else cp_wait0();
        __syncthreads();
        if (c + 3 < NCH) issue_loads(c + 3, (c + 3) & 3);

        const uint32_t st = dbase + (uint32_t)s * STAGE;
        const uint32_t aB = st + aOff;
        const uint32_t bB = st + bOff;
        uint32_t a[4][4], b[4][2];
#pragma unroll
        for (int mi = 0; mi < 4; ++mi)
            ldm_x4(a[mi], aB + mi * 16 * SSTR);
#pragma unroll
        for (int ni = 0; ni < 4; ++ni)
            ldm_x2(b[ni], bB + ni * 8 * SSTR);
#pragma unroll
        for (int mi = 0; mi < 4; ++mi)
#pragma unroll
            for (int ni = 0; ni < 4; ++ni)
                imma16832(acc[mi][ni], a[mi], b[ni]);
    }

    // ---- epilogue ----
    const int trow = lane >> 2, tcol = (lane & 3) * 2;
#pragma unroll
    for (int mi = 0; mi < 4; ++mi) {
        const int mA = bm + wm * 64 + mi * 16 + trow;
        const int mB = mA + 8;
        int aidA = 0, aidB = 0;
        if (MASK) { aidA = adapter_ids[mA]; aidB = adapter_ids[mB]; }
#pragma unroll
        for (int ni = 0; ni < 4; ++ni) {
            const int n = bn + wn * 32 + ni * 8 + tcol;
            float* pA = C + (size_t)mA * ldc + n;
            float* pB = C + (size_t)mB * ldc + n;
            float2 vA = make_float2(scale * (float)acc[mi][ni][0],
                                    scale * (float)acc[mi][ni][1]);
            float2 vB = make_float2(scale * (float)acc[mi][ni][2],
                                    scale * (float)acc[mi][ni][3]);
            if (CROSS) {
                const float2 oA = *(const float2*)pA;
                const float2 oB = *(const float2*)pB;
                vA.x += oA.x; vA.y += oA.y;
                vB.x += oB.x; vB.y += oB.y;
            } else if (!MASK) {
                const float2 bz = *(const float2*)(bias + n);
                vA.x += bz.x; vA.y += bz.y;
                vB.x += bz.x; vB.y += bz.y;
            }
            if (MASK) {
                const int slot = n >> 6;          // n, n+1 share the slot (n even)
                if (slot != aidA) { vA.x = 0.0f; vA.y = 0.0f; }
                if (slot != aidB) { vB.x = 0.0f; vB.y = 0.0f; }
            }
            *(float2*)pA = vA;
            *(float2*)pB = vB;
        }
    }
}

// ---------------- launch ----------------
extern "C" void kernel_launch(void* const* d_in, const int* in_sizes, int n_in,
                              void* d_out, int out_size)
{
    const float* x           = (const float*)d_in[0];
    const float* w           = (const float*)d_in[1];
    const float* bias        = (const float*)d_in[2];
    const float* a_cache     = (const float*)d_in[3];
    const float* b_cache     = (const float*)d_in[4];
    const int*   adapter_ids = (const int*)d_in[5];
    const int*   page        = (const int*)d_in[6];
    const int*   ranks       = (const int*)d_in[7];
    float*       out         = (float*)d_out;

    signed char *pAq, *pBq, *pB1q;
    float* pxa;
    cudaGetSymbolAddress((void**)&pAq,  g_Aq);
    cudaGetSymbolAddress((void**)&pBq,  g_Bq);
    cudaGetSymbolAddress((void**)&pB1q, g_B1q);
    cudaGetSymbolAddress((void**)&pxa,  g_xa);

    cudaFuncSetAttribute(imma_gemm<true,  false>, cudaFuncAttributeMaxDynamicSharedMemorySize, DSMEM);
    cudaFuncSetAttribute(imma_gemm<true,  true >, cudaFuncAttributeMaxDynamicSharedMemorySize, DSMEM);
    cudaFuncSetAttribute(imma_gemm<false, false>, cudaFuncAttributeMaxDynamicSharedMemorySize, DSMEM);
    cudaFuncSetAttribute(imma_gemm<false, true >, cudaFuncAttributeMaxDynamicSharedMemorySize, DSMEM);

    // quantize operands (2-plane int8)
    pack_x <<<(T_TOK * DIN) / 4 / 256, 256>>>(x);
    pack_w <<<(DOUT * DIN) / 4 / 256, 256>>>(w);
    pack_bt<<<(DOUT * CL)  / 4 / 256, 256>>>(b_cache, page);
    pack_b1<<<(CL * DIN)   / 4 / 256, 256>>>(a_cache, page, ranks);

    // gemm1: xa = mask(x @ Acat^T)   (main + cross passes; xa cols hit zero B1 cols)
    imma_gemm<true, false><<<dim3(CL / 128, T_TOK / 128), 256, DSMEM>>>(
        pAq, pB1q, nullptr, adapter_ids, pxa, CL, S_MAIN);
    imma_gemm<true, true><<<dim3(CL / 128, T_TOK / 128), 256, DSMEM>>>(
        pAq, pB1q, nullptr, adapter_ids, pxa, CL, S_CROSS);

    // quantize xa into A operand columns
    pack_xa<<<(T_TOK * CL) / 4 / 256, 256>>>();

    // gemm2: out = x @ W^T + xa @ BT^T + bias   (main writes +bias, cross adds)
    imma_gemm<false, false><<<dim3(DOUT / 128, T_TOK / 128), 256, DSMEM>>>(
        pAq, pBq, bias, nullptr, out, DOUT, S_MAIN);
    imma_gemm<false, true><<<dim3(DOUT / 128, T_TOK / 128), 256, DSMEM>>>(
        pAq, pBq, bias, nullptr, out, DOUT, S_CROSS);
}

// round 11
// speedup vs baseline: 5.7929x; 5.7929x over previous
#include <cuda_runtime.h>
#include <cuda_fp16.h>
#include <cstdint>

// ---------------- problem constants ----------------
#define T_TOK 8192
#define DIN   4096
#define DOUT  4096
#define CL    256                  // NUM_ADAPTERS * MAX_RANK pages
#define KSEG  (DIN + CL)           // 4352: single fp16 segment (x | xa)
#define BK    32
#define KCH   (KSEG / BK)          // 136 chunks

#define SSTRIDE 40                 // smem row stride in fp16 (80B: conflict-free ldmatrix)
#define ATILE_B (128 * SSTRIDE * 2)       // 10240 B per A (or B) stage tile
#define STAGE_B (2 * ATILE_B)             // 20480 B per pipeline stage
#define NSTAGE  3
#define DSMEM_B (NSTAGE * STAGE_B)        // 61440 B dynamic smem

// ---------------- device scratch (no allocs; zero-initialized) ----------------
__device__ __half g_A2[(size_t)T_TOK * KSEG];   // row t: [x(4096) | xa(256)] fp16
__device__ __half g_B2[(size_t)DOUT * KSEG];    // row n: [W | BT]
__device__ __half g_B1[(size_t)CL * KSEG];      // row j: [Acat | 0(256)] (zeros never written)
__device__ float  g_xa[(size_t)T_TOK * CL];     // gemm1 output (fp32)

// ---------------- generic-PTX helpers (sm_80+) ----------------
__device__ __forceinline__ uint32_t smem_u32(const void* p) {
    uint32_t a;
    asm("{ .reg .u64 t; cvta.to.shared.u64 t, %1; cvt.u32.u64 %0, t; }" : "=r"(a) : "l"(p));
    return a;
}
__device__ __forceinline__ void cp_async16(uint32_t saddr, const void* gaddr) {
    asm volatile("cp.async.cg.shared.global [%0], [%1], 16;" :: "r"(saddr), "l"(gaddr));
}
__device__ __forceinline__ void cp_commit() { asm volatile("cp.async.commit_group;"); }
__device__ __forceinline__ void cp_wait1()  { asm volatile("cp.async.wait_group 1;" ::: "memory"); }
__device__ __forceinline__ void cp_wait0()  { asm volatile("cp.async.wait_group 0;" ::: "memory"); }

__device__ __forceinline__ void ldm_x4(uint32_t* r, uint32_t addr) {
    asm volatile("ldmatrix.sync.aligned.m8n8.x4.shared.b16 {%0,%1,%2,%3}, [%4];"
                 : "=r"(r[0]), "=r"(r[1]), "=r"(r[2]), "=r"(r[3]) : "r"(addr));
}
__device__ __forceinline__ void ldm_x2(uint32_t* r, uint32_t addr) {
    asm volatile("ldmatrix.sync.aligned.m8n8.x2.shared.b16 {%0,%1}, [%2];"
                 : "=r"(r[0]), "=r"(r[1]) : "r"(addr));
}
__device__ __forceinline__ void mma16816(float* c, const uint32_t* a, const uint32_t* b) {
    asm volatile(
        "mma.sync.aligned.m16n8k16.row.col.f32.f16.f16.f32 "
        "{%0,%1,%2,%3}, {%4,%5,%6,%7}, {%8,%9}, {%0,%1,%2,%3};"
        : "+f"(c[0]), "+f"(c[1]), "+f"(c[2]), "+f"(c[3])
        : "r"(a[0]), "r"(a[1]), "r"(a[2]), "r"(a[3]), "r"(b[0]), "r"(b[1]));
}

// ---------------- packing kernels (fp32 -> fp16, single plane) ----------------
__global__ void pack_x(const float* __restrict__ x) {
    size_t i4 = ((size_t)blockIdx.x * blockDim.x + threadIdx.x) * 4;
    size_t t = i4 / DIN, k = i4 % DIN;
    float4 v = *(const float4*)(x + i4);
    __half2 h01 = __floats2half2_rn(v.x, v.y);
    __half2 h23 = __floats2half2_rn(v.z, v.w);
    __half* row = g_A2 + t * KSEG;
    *(__half2*)(row + k)     = h01;
    *(__half2*)(row + k + 2) = h23;
}
__global__ void pack_w(const float* __restrict__ w) {
    size_t i4 = ((size_t)blockIdx.x * blockDim.x + threadIdx.x) * 4;
    size_t n = i4 / DIN, k = i4 % DIN;
    float4 v = *(const float4*)(w + i4);
    __half2 h01 = __floats2half2_rn(v.x, v.y);
    __half2 h23 = __floats2half2_rn(v.z, v.w);
    __half* row = g_B2 + n * KSEG;
    *(__half2*)(row + k)     = h01;
    *(__half2*)(row + k + 2) = h23;
}
__global__ void pack_bt(const float* __restrict__ b_cache, const int* __restrict__ page) {
    size_t idx = (size_t)blockIdx.x * blockDim.x + threadIdx.x;   // DOUT*CL threads
    size_t n = idx / CL, j = idx % CL;
    g_B2[n * KSEG + DIN + j] = __float2half_rn(b_cache[(size_t)page[j] * DOUT + n]);
}
__global__ void pack_b1(const float* __restrict__ a_cache, const int* __restrict__ page,
                        const int* __restrict__ ranks) {
    size_t i4 = ((size_t)blockIdx.x * blockDim.x + threadIdx.x) * 4;
    size_t j = i4 / DIN, k = i4 % DIN;
    int a = (int)(j >> 6), r = (int)(j & 63);
    float am = (r < ranks[a]) ? 1.0f : 0.0f;
    float4 v = *(const float4*)(a_cache + (size_t)page[j] * DIN + k);
    __half2 h01 = __floats2half2_rn(am * v.x, am * v.y);
    __half2 h23 = __floats2half2_rn(am * v.z, am * v.w);
    __half* row = g_B1 + j * KSEG;
    *(__half2*)(row + k)     = h01;
    *(__half2*)(row + k + 2) = h23;
}
__global__ void pack_xa() {
    size_t i4 = ((size_t)blockIdx.x * blockDim.x + threadIdx.x) * 4;
    size_t t = i4 / CL, j = i4 % CL;
    float4 v = *(const float4*)(g_xa + i4);
    __half2 h01 = __floats2half2_rn(v.x, v.y);
    __half2 h23 = __floats2half2_rn(v.z, v.w);
    __half* row = g_A2 + t * KSEG;
    *(__half2*)(row + DIN + j)     = h01;
    *(__half2*)(row + DIN + j + 2) = h23;
}

// ---------------- mma.sync GEMM: C[M,N] = A[M,KSEG] @ B[N,KSEG]^T ----------------
// CTA 128x128, BK=32, 8 warps (2x4), warp tile 64x32, m16n8k16 f16 -> fp32.
// 3-stage cp.async pipeline, arithmetic stage addressing (no local-mem arrays).
// MASK=true: gemm1 (adapter mask); false: gemm2 (+bias).
template <bool MASK>
__global__ __launch_bounds__(256, 2)
void mma_gemm(const __half* __restrict__ A,
              const __half* __restrict__ B,
              const float* __restrict__ bias,
              const int* __restrict__ adapter_ids,
              float* __restrict__ C, int ldc)
{
    extern __shared__ char dsm[];

    const int tid  = threadIdx.x;
    const int lane = tid & 31;
    const int wid  = tid >> 5;
    const int wm   = wid >> 2;          // 0..1 -> warp row (64 rows)
    const int wn   = wid & 3;           // 0..3 -> warp col (32 cols)
    const int bm   = blockIdx.y * 128;
    const int bn   = blockIdx.x * 128;

    // ---- cp.async tile-fill maps: 512 16B-units per tile, 2 per thread ----
    const int u0 = tid, u1 = tid + 256;
    const int r0 = u0 >> 2, n0u = u0 & 3;
    const int r1 = u1 >> 2, n1u = u1 & 3;

    const __half* Ag0 = A + (size_t)(bm + r0) * KSEG + n0u * 8;
    const __half* Ag1 = A + (size_t)(bm + r1) * KSEG + n1u * 8;
    const __half* Bg0 = B + (size_t)(bn + r0) * KSEG + n0u * 8;
    const __half* Bg1 = B + (size_t)(bn + r1) * KSEG + n1u * 8;

    const uint32_t dbase = smem_u32(dsm);
    const uint32_t offA0 = (r0 * SSTRIDE + n0u * 8) * 2;
    const uint32_t offA1 = (r1 * SSTRIDE + n1u * 8) * 2;
    const uint32_t offB0 = ATILE_B + (r0 * SSTRIDE + n0u * 8) * 2;
    const uint32_t offB1 = ATILE_B + (r1 * SSTRIDE + n1u * 8) * 2;
    // ldmatrix bases: A x4 row = wm*64 + (lane&15), col8 = lane>>4
    //                 B x2 row = wn*32 + (lane&7),  col8 = (lane>>3)&1
    const uint32_t aOff = ((wm * 64 + (lane & 15)) * SSTRIDE + (lane >> 4) * 8) * 2;
    const uint32_t bOff = ATILE_B + ((wn * 32 + (lane & 7)) * SSTRIDE + ((lane >> 3) & 1) * 8) * 2;

    float acc[4][4][4];
#pragma unroll
    for (int mi = 0; mi < 4; ++mi)
#pragma unroll
        for (int ni = 0; ni < 4; ++ni)
#pragma unroll
            for (int q = 0; q < 4; ++q) acc[mi][ni][q] = 0.0f;

    auto issue_loads = [&](int c, int s) {
        const uint32_t st = dbase + (uint32_t)s * STAGE_B;
        const size_t k0 = (size_t)c * BK;
        cp_async16(st + offA0, Ag0 + k0);
        cp_async16(st + offA1, Ag1 + k0);
        cp_async16(st + offB0, Bg0 + k0);
        cp_async16(st + offB1, Bg1 + k0);
        cp_commit();
    };

    // prologue: stages 0,1 in flight
    issue_loads(0, 0);
    issue_loads(1, 1);

    int s = 0;                       // stage of chunk c
    int s2 = 2;                      // stage of chunk c+2
    for (int c = 0; c < KCH; ++c) {
        if (c + 2 < KCH) cp_wait1(); else cp_wait0();
        __syncthreads();
        if (c + 2 < KCH) issue_loads(c + 2, s2);

        const uint32_t st = dbase + (uint32_t)s * STAGE_B;
        const uint32_t aB = st + aOff;
        const uint32_t bB = st + bOff;
#pragma unroll
        for (int ks = 0; ks < 2; ++ks) {
            uint32_t a[4][4], b[4][2];
#pragma unroll
            for (int mi = 0; mi < 4; ++mi)
                ldm_x4(a[mi], aB + (mi * 16 * SSTRIDE + ks * 16) * 2);
#pragma unroll
            for (int ni = 0; ni < 4; ++ni)
                ldm_x2(b[ni], bB + (ni * 8 * SSTRIDE + ks * 16) * 2);
#pragma unroll
            for (int mi = 0; mi < 4; ++mi)
#pragma unroll
                for (int ni = 0; ni < 4; ++ni)
                    mma16816(acc[mi][ni], a[mi], b[ni]);
        }

        s  = (s  == NSTAGE - 1) ? 0 : s  + 1;
        s2 = (s2 == NSTAGE - 1) ? 0 : s2 + 1;
    }

    // ---- epilogue ----
    const int trow = lane >> 2, tcol = (lane & 3) * 2;
#pragma unroll
    for (int mi = 0; mi < 4; ++mi) {
        const int mA = bm + wm * 64 + mi * 16 + trow;
        const int mB = mA + 8;
        int aidA = 0, aidB = 0;
        if (MASK) { aidA = adapter_ids[mA]; aidB = adapter_ids[mB]; }
#pragma unroll
        for (int ni = 0; ni < 4; ++ni) {
            const int n = bn + wn * 32 + ni * 8 + tcol;
            float2 vA = make_float2(acc[mi][ni][0], acc[mi][ni][1]);
            float2 vB = make_float2(acc[mi][ni][2], acc[mi][ni][3]);
            if (MASK) {
                const int slot = n >> 6;          // n, n+1 share the slot (n even)
                if (slot != aidA) { vA.x = 0.0f; vA.y = 0.0f; }
                if (slot != aidB) { vB.x = 0.0f; vB.y = 0.0f; }
            } else {
                const float2 bz = *(const float2*)(bias + n);
                vA.x += bz.x; vA.y += bz.y;
                vB.x += bz.x; vB.y += bz.y;
            }
            *(float2*)(C + (size_t)mA * ldc + n) = vA;
            *(float2*)(C + (size_t)mB * ldc + n) = vB;
        }
    }
}

// ---------------- launch ----------------
extern "C" void kernel_launch(void* const* d_in, const int* in_sizes, int n_in,
                              void* d_out, int out_size)
{
    const float* x           = (const float*)d_in[0];
    const float* w           = (const float*)d_in[1];
    const float* bias        = (const float*)d_in[2];
    const float* a_cache     = (const float*)d_in[3];
    const float* b_cache     = (const float*)d_in[4];
    const int*   adapter_ids = (const int*)d_in[5];
    const int*   page        = (const int*)d_in[6];
    const int*   ranks       = (const int*)d_in[7];
    float*       out         = (float*)d_out;

    __half *pA2, *pB2, *pB1;
    float* pxa;
    cudaGetSymbolAddress((void**)&pA2, g_A2);
    cudaGetSymbolAddress((void**)&pB2, g_B2);
    cudaGetSymbolAddress((void**)&pB1, g_B1);
    cudaGetSymbolAddress((void**)&pxa, g_xa);

    cudaFuncSetAttribute(mma_gemm<true>,
                         cudaFuncAttributeMaxDynamicSharedMemorySize, DSMEM_B);
    cudaFuncSetAttribute(mma_gemm<false>,
                         cudaFuncAttributeMaxDynamicSharedMemorySize, DSMEM_B);

    // pack operands (fp32 -> fp16, gathers)
    pack_x <<<(T_TOK * DIN) / 4 / 256, 256>>>(x);
    pack_w <<<(DOUT * DIN) / 4 / 256, 256>>>(w);
    pack_bt<<<(DOUT * CL)      / 256, 256>>>(b_cache, page);
    pack_b1<<<(CL * DIN)   / 4 / 256, 256>>>(a_cache, page, ranks);

    // gemm1: g_xa[8192,256] = adapter-mask(x @ Acat^T)  (xa cols hit zero B1 cols)
    mma_gemm<true><<<dim3(CL / 128, T_TOK / 128), 256, DSMEM_B>>>(
        pA2, pB1, nullptr, adapter_ids, pxa, CL);

    // insert xa (fp16) into A operand columns
    pack_xa<<<(T_TOK * CL) / 4 / 256, 256>>>();

    // gemm2: out = x @ W^T + xa @ BT^T + bias  (single-pass fp16, K=4352)
    mma_gemm<false><<<dim3(DOUT / 128, T_TOK / 128), 256, DSMEM_B>>>(
        pA2, pB2, bias, nullptr, out, DOUT);
}